// round 6
// baseline (speedup 1.0000x reference)
#include <cuda_runtime.h>
#include <math.h>

#define Bv   64
#define Tv   500
#define Hh   128
#define Kk   32
#define NSK  101    /* N_SK+1 */
#define BT   (Bv*Tv)

typedef unsigned long long ull;

/* ---------------- scratch (device globals; no allocation) ---------------- */
__device__ float d_sedata [BT*Hh];
__device__ float d_selearn[BT*Hh];
__device__ float d_gx     [BT*3*Hh];
__device__ float d_preg   [BT*Hh];
__device__ float d_pregg  [BT*Hh];
__device__ float d_wall   [BT*Kk];
__device__ float d_gruout [BT*Hh];
__device__ float d_out1   [Bv*(Tv-1)*Hh];

__device__ float d_W1T [256*128];
__device__ float d_W2T [384*128];
__device__ float d_W3T [256*128];
__device__ float d_WihT[128*384];
__device__ float d_keyT[128*32];
__device__ float d_WGgP[128*256];   /* pair-interleaved: (j,o) -> [(j>>1)*512 + o*2 + (j&1)] */
__device__ float d_WgTl [128*128];
__device__ float d_WggTl[128*128];
__device__ float d_WfaP [128*128];  /* Wf[:, :128] pair-interleaved: [(j>>1)*256 + h*2 + (j&1)] */
__device__ float d_WfbP [128*128];  /* Wf[:, 128:] pair-interleaved */
__device__ float d_whhT [128*384];

__device__ __forceinline__ float sigm(float x){ return 1.f/(1.f+expf(-x)); }

__device__ __forceinline__ void fma2(ull &d, ull a, ull b){
    asm("fma.rn.f32x2 %0, %1, %2, %0;" : "+l"(d) : "l"(a), "l"(b));
}
__device__ __forceinline__ float sum2(ull v){
    return __uint_as_float((unsigned)v) + __uint_as_float((unsigned)(v>>32));
}

/* 16-row hs swizzle: chunk (h>>2) XOR ((k>>1)&7) */
__device__ __forceinline__ int hsw16(int k, int h){
    return k*128 + ((((h>>2) ^ ((k>>1)&7)))<<2) + (h&3);
}

__device__ __forceinline__ unsigned smem_u32(const void* p){
    unsigned a;
    asm("{ .reg .u64 t; cvta.to.shared.u64 t, %1; cvt.u32.u64 %0, t; }" : "=r"(a) : "l"(p));
    return a;
}
__device__ __forceinline__ unsigned mapa_peer(unsigned addr, unsigned rank){
    unsigned r; asm("mapa.shared::cluster.u32 %0, %1, %2;" : "=r"(r) : "r"(addr), "r"(rank));
    return r;
}
__device__ __forceinline__ void st_cluster_f32(unsigned addr, float v){
    asm volatile("st.shared::cluster.f32 [%0], %1;" :: "r"(addr), "f"(v) : "memory");
}
__device__ __forceinline__ unsigned ctarank(){
    unsigned r; asm("mov.u32 %0, %%cluster_ctarank;" : "=r"(r)); return r;
}
#define CLUSTER_BAR() do{ \
    asm volatile("barrier.cluster.arrive.aligned;" ::: "memory"); \
    asm volatile("barrier.cluster.wait.aligned;"   ::: "memory"); }while(0)

/* ---------------- weight pre-transpose / pair-interleave ---------------- */
__global__ void prep_kernel(const float* W1, const float* W2, const float* W3,
                            const float* key, const float* wih, const float* whh,
                            const float* Wg, const float* Wgg, const float* Wf)
{
    int stride = gridDim.x*blockDim.x;
    int t0 = blockIdx.x*blockDim.x + threadIdx.x;
    for (int i=t0;i<256*128;i+=stride){ int j=i>>7,h=i&127; d_W1T[i]=W1[h*256+j]; d_W3T[i]=W3[h*256+j]; }
    for (int i=t0;i<384*128;i+=stride){ int j=i>>7,h=i&127; d_W2T[i]=W2[h*384+j]; }
    for (int i=t0;i<128*384;i+=stride){ int h=i/384,g=i%384; d_WihT[i]=wih[g*128+h]; d_whhT[i]=whh[g*128+h]; }
    for (int i=t0;i<128*32;i+=stride){ int h=i>>5,k=i&31; d_keyT[i]=key[k*128+h]; }
    for (int i=t0;i<128*256;i+=stride){ int j=i>>8,o=i&255;
        d_WGgP[(j>>1)*512 + o*2 + (j&1)] = (o<128)? Wg[o*256+j] : Wgg[(o-128)*256+j]; }
    for (int i=t0;i<128*128;i+=stride){ int j=i>>7,h=i&127;
        d_WgTl[i]=Wg[h*256+128+j]; d_WggTl[i]=Wgg[h*256+128+j];
        d_WfaP[(j>>1)*256 + h*2 + (j&1)] = Wf[h*256+j];
        d_WfbP[(j>>1)*256 + h*2 + (j&1)] = Wf[h*256+128+j]; }
}

/* ---------------- fused parallel phase (unchanged, passing) ---------------- */
__global__ void __launch_bounds__(256) fused_kernel(
    const int* e_data, const int* a_data, const float* qm, const float* semb_w,
    const float* aemb_w, const float* eemb_w,
    const float* b1, const float* b2, const float* b3,
    const float* bih, const float* bg, const float* bgg)
{
    __shared__ float X [16*384];
    __shared__ float sd[16*128];
    __shared__ float sl[16*128];
    int tid = threadIdx.x;
    int h = tid & 127, rh = tid >> 7;
    int base = blockIdx.x*16;
    int rbase = rh*8;

    for (int r8=0;r8<8;r8++){
        int rr = rbase + r8; int row = base + rr;
        int e = e_data[row], a = a_data[row];
        const float* qrow = qm + (size_t)e*NSK;
        float acc=0.f, cnt=0.f;
        #pragma unroll 4
        for (int s=0;s<NSK;s++){ float q = qrow[s]; acc += q*semb_w[s*128+h]; cnt += q; }
        if (cnt==0.f) cnt=1.f;
        X[rr*384+h]       = acc/cnt;
        X[rr*384+128+h]   = eemb_w[e*128+h];
        X[rr*384+256+h]   = aemb_w[a*128+h];
    }
    __syncthreads();

    {
        float acc[8];
        #pragma unroll
        for(int r=0;r<8;r++)acc[r]=b1[h];
        #pragma unroll 4
        for (int j=0;j<256;j++){ float w = d_W1T[j*128+h];
            #pragma unroll
            for (int r=0;r<8;r++) acc[r] += X[(rbase+r)*384 + j]*w; }
        #pragma unroll
        for (int r=0;r<8;r++){ float v=fmaxf(acc[r],0.f);
            sd[(rbase+r)*128+h]=v; d_sedata[(base+rbase+r)*128+h]=v; }
    }
    {
        float acc[8];
        #pragma unroll
        for(int r=0;r<8;r++)acc[r]=b2[h];
        #pragma unroll 4
        for (int j=0;j<384;j++){ float w = d_W2T[j*128+h];
            #pragma unroll
            for (int r=0;r<8;r++) acc[r] += X[(rbase+r)*384 + j]*w; }
        #pragma unroll
        for (int r=0;r<8;r++){ float v=fmaxf(acc[r],0.f);
            sl[(rbase+r)*128+h]=v; d_selearn[(base+rbase+r)*128+h]=v; }
    }
    float el[8];
    {
        float acc[8];
        #pragma unroll
        for(int r=0;r<8;r++)acc[r]=b3[h];
        #pragma unroll 4
        for (int j=0;j<256;j++){ float w = d_W3T[j*128+h];
            #pragma unroll
            for (int r=0;r<8;r++) acc[r] += X[(rbase+r)*384 + 128 + j]*w; }
        #pragma unroll
        for (int r=0;r<8;r++) el[r] = fmaxf(acc[r],0.f);
    }
    __syncthreads();
    #pragma unroll
    for (int r=0;r<8;r++) X[(rbase+r)*128 + h] = el[r];
    __syncthreads();

    for (int p=0;p<3;p++){
        int g = p*128+h;
        float acc[8];
        #pragma unroll
        for(int r=0;r<8;r++)acc[r]=bih[g];
        #pragma unroll 4
        for (int j=0;j<128;j++){ float w = d_WihT[j*384+g];
            #pragma unroll
            for (int r=0;r<8;r++) acc[r] += X[(rbase+r)*128+j]*w; }
        #pragma unroll
        for (int r=0;r<8;r++) d_gx[(base+rbase+r)*384 + g] = acc[r];
    }
    {
        float a1[8],a2[8];
        #pragma unroll
        for(int r=0;r<8;r++){a1[r]=bg[h]; a2[r]=bgg[h];}
        #pragma unroll 4
        for (int j=0;j<128;j++){ float w1=d_WgTl[j*128+h], w2=d_WggTl[j*128+h];
            #pragma unroll
            for (int r=0;r<8;r++){ float x=sl[(rbase+r)*128+j]; a1[r]+=x*w1; a2[r]+=x*w2; } }
        #pragma unroll
        for (int r=0;r<8;r++){ d_preg[(base+rbase+r)*128+h]=a1[r]; d_pregg[(base+rbase+r)*128+h]=a2[r]; }
    }
    if (tid < 64){
        int k = tid & 31; int rh2 = tid >> 5; int rb2 = rh2*8;
        float acc[8];
        #pragma unroll
        for(int r=0;r<8;r++)acc[r]=0.f;
        #pragma unroll 4
        for (int j=0;j<128;j++){ float w = d_keyT[j*32+k];
            #pragma unroll
            for (int r=0;r<8;r++) acc[r] += sd[(rb2+r)*128+j]*w; }
        #pragma unroll
        for (int r=0;r<8;r++) d_wall[(base+rb2+r)*32 + k] = acc[r];
    }
}

/* ---------------- scans: blocks 0..127 = memory scan (clusters of 2 per batch),
                    blocks 128..191 = GRU ---------------- */
#define SMEM_FLOATS 51968   /* 207872 bytes */

__global__ void __launch_bounds__(512) __cluster_dims__(2,1,1) scan_kernel(
    const float* h0, const float* m0, const float* bf, const float* bhh)
{
    extern __shared__ float sm[];
    int tid = threadIdx.x;
    int bid = blockIdx.x;

    if (bid < 128) {
        /* ------- memory scan: batch b split over 2 CTAs (16 K-rows each) ------- */
        int b = bid >> 1;
        unsigned rank = ctarank();           /* 0 or 1 */
        float* WGg  = sm;                    /* 32768 */
        float* Wfa  = sm + 32768;            /* 16384 */
        float* hs   = sm + 49152;            /* 2048 : 16x128 swizzled */
        float* htvS = sm + 51200;            /* 128 : own partial -> summed ht */
        float* LG   = sm + 51328;            /* 128 */
        float* cv   = sm + 51456;            /* 128 */
        float* gA   = sm + 51584;            /* 256 */
        float* htpR = sm + 51840;            /* 128 : peer's partial (written remotely) */

        for (int i=tid;i<32768;i+=512) WGg[i] = d_WGgP[i];
        for (int i=tid;i<16384;i+=512) Wfa[i] = d_WfaP[i];
        for (int i=tid;i<2048; i+=512){ int k=i>>7, h=i&127;
            hs[hsw16(k,h)] = m0[(rank*16+k)*128 + h]; }
        __syncthreads();

        unsigned htpR_peer = mapa_peer(smem_u32(htpR), rank^1u);

        /* ht0 partial over own 16 rows */
        if (tid < 128){
            float acc=0.f; const float* w0 = d_wall + b*Tv*Kk + rank*16;
            #pragma unroll 4
            for (int k=0;k<16;k++) acc += w0[k]*hs[hsw16(k,tid)];
            htvS[tid]=acc;
            st_cluster_f32(htpR_peer + tid*4u, acc);
        }
        CLUSTER_BAR();

        if (tid < 256){
            /* ============ C-group: GEMM (2k x 4h per thread) + epilogue ============ */
            int w = tid >> 5, l = tid & 31;
            int kq = l >> 2, hq = w*4 + (l & 3);
            int k0 = kq*2, h0i = hq*4;
            int pc = ((hq ^ kq) & 31) << 2;

            float2 wA2 = *(const float2*)&d_wall[(b*Tv  )*32 + rank*16 + k0];
            float2 wB2 = *(const float2*)&d_wall[(b*Tv+1)*32 + rank*16 + k0];

            for (int t=0;t<Tv-1;t++){
                ull acc2[2][4];
                #pragma unroll
                for (int a=0;a<2;a++){
                    #pragma unroll
                    for (int c=0;c<4;c++) acc2[a][c]=0ull;
                }
                {
                    const float* wbase = Wfa + h0i*2;
                    #pragma unroll 4
                    for (int jg=0;jg<32;jg++){
                        float4 wA0 = *(const float4*)&wbase[(2*jg  )*256];
                        float4 wB0 = *(const float4*)&wbase[(2*jg  )*256 + 4];
                        float4 wA1 = *(const float4*)&wbase[(2*jg+1)*256];
                        float4 wB1 = *(const float4*)&wbase[(2*jg+1)*256 + 4];
                        ull wA0a = ((ull*)&wA0)[0], wA0b = ((ull*)&wA0)[1];
                        ull wB0a = ((ull*)&wB0)[0], wB0b = ((ull*)&wB0)[1];
                        ull wA1a = ((ull*)&wA1)[0], wA1b = ((ull*)&wA1)[1];
                        ull wB1a = ((ull*)&wB1)[0], wB1b = ((ull*)&wB1)[1];
                        int sc = ((jg ^ kq) << 2);
                        #pragma unroll
                        for (int kk=0;kk<2;kk++){
                            float4 hp4 = *(const float4*)&hs[(k0+kk)*128 + sc];
                            ull hp01 = ((ull*)&hp4)[0], hp23 = ((ull*)&hp4)[1];
                            fma2(acc2[kk][0], hp01, wA0a);
                            fma2(acc2[kk][1], hp01, wA0b);
                            fma2(acc2[kk][2], hp01, wB0a);
                            fma2(acc2[kk][3], hp01, wB0b);
                            fma2(acc2[kk][0], hp23, wA1a);
                            fma2(acc2[kk][1], hp23, wA1b);
                            fma2(acc2[kk][2], hp23, wB1a);
                            fma2(acc2[kk][3], hp23, wB1b);
                        }
                    }
                }
                asm volatile("bar.sync 2, 512;" ::: "memory");   /* LG+cv ready */
                {
                    float4 lg4 = *(const float4*)&LG[h0i];
                    float4 cv4 = *(const float4*)&cv[h0i];
                    float pr[4]={0.f,0.f,0.f,0.f};
                    #pragma unroll
                    for (int kk=0;kk<2;kk++){
                        float wtk = kk? wA2.y : wA2.x;
                        float wnk = kk? wB2.y : wB2.x;
                        float* row = &hs[(k0+kk)*128 + pc];
                        float4 hv4 = *(float4*)row;
                        float4 nv;
                        nv.x = sigm(sum2(acc2[kk][0]) + cv4.x)*hv4.x + wtk*lg4.x;
                        nv.y = sigm(sum2(acc2[kk][1]) + cv4.y)*hv4.y + wtk*lg4.y;
                        nv.z = sigm(sum2(acc2[kk][2]) + cv4.z)*hv4.z + wtk*lg4.z;
                        nv.w = sigm(sum2(acc2[kk][3]) + cv4.w)*hv4.w + wtk*lg4.w;
                        *(float4*)row = nv;
                        pr[0] += wnk*nv.x; pr[1] += wnk*nv.y;
                        pr[2] += wnk*nv.z; pr[3] += wnk*nv.w;
                    }
                    #pragma unroll
                    for (int off=16;off>=4;off>>=1){
                        #pragma unroll
                        for (int a=0;a<4;a++) pr[a] += __shfl_xor_sync(0xffffffffu, pr[a], off);
                    }
                    if (l < 4){
                        int hb = (w*4 + l)*4;
                        float4 st; st.x=pr[0]; st.y=pr[1]; st.z=pr[2]; st.w=pr[3];
                        *(float4*)&htvS[hb] = st;
                        st_cluster_f32(htpR_peer + (hb+0)*4u, pr[0]);
                        st_cluster_f32(htpR_peer + (hb+1)*4u, pr[1]);
                        st_cluster_f32(htpR_peer + (hb+2)*4u, pr[2]);
                        st_cluster_f32(htpR_peer + (hb+3)*4u, pr[3]);
                    }
                    wA2 = wB2;
                    if (t+2 < Tv) wB2 = *(const float2*)&d_wall[(b*Tv+t+2)*32 + rank*16 + k0];
                }
                CLUSTER_BAR();
            }
        } else {
            /* ============ AB-group: sum partials + gates + LG + cv ============ */
            int o = tid - 256;                 /* 0..255 */
            float pfg=0.f, pfgg=0.f;
            if (o < 128){
                pfg  = d_preg [(b*Tv)*128+o];
                pfgg = d_pregg[(b*Tv)*128+o];
            }
            for (int t=0;t<Tv-1;t++){
                if (o < 128){
                    float s = htvS[o] + htpR[o];
                    htvS[o] = s;
                    if (rank==0 && t>0) d_out1[(size_t)(b*(Tv-1)+t-1)*128 + o] = s;
                }
                asm volatile("bar.sync 1, 256;" ::: "memory");   /* htvS summed */
                /* A) gate preact: one f32x2 dot per thread */
                {
                    ull acc = 0;
                    const float* wrow = WGg + o*2;
                    #pragma unroll 16
                    for (int jp=0;jp<64;jp++){
                        ull h2 = *(const ull*)&htvS[jp*2];
                        ull w2 = *(const ull*)&wrow[jp*512];
                        fma2(acc, h2, w2);
                    }
                    gA[o] = sum2(acc);
                }
                asm volatile("bar.sync 1, 256;" ::: "memory");
                if (o < 128){
                    LG[o] = tanhf(gA[o]+pfg)*sigm(gA[128+o]+pfgg);
                    pfg  = d_preg [(b*Tv+t+1)*128+o];
                    pfgg = d_pregg[(b*Tv+t+1)*128+o];
                    asm volatile("bar.sync 3, 128;" ::: "memory");
                    /* B) cv = Wf_b @ LG + bf (weights streamed from L2) */
                    ull acc = 0;
                    const float* wrow = d_WfbP + o*2;
                    #pragma unroll 16
                    for (int jp=0;jp<64;jp++){
                        ull lg2 = *(const ull*)&LG[jp*2];
                        ull w2  = *(const ull*)&wrow[jp*256];
                        fma2(acc, lg2, w2);
                    }
                    cv[o] = sum2(acc) + bf[o];
                }
                asm volatile("bar.arrive 2, 512;" ::: "memory");
                CLUSTER_BAR();
            }
        }
        /* final out1 row: ht produced by last epilogue */
        if (tid < 128 && rank==0){
            float s = htvS[tid] + htpR[tid];
            d_out1[(size_t)(b*(Tv-1)+Tv-2)*128 + tid] = s;
        }
    } else {
        /* ------------- GRU scan (one batch per CTA) ------------- */
        int b = bid - 128;
        float* whh = sm;            /* 49152 : w_hh^T [j][384] */
        float* hv  = sm + 49152;    /* 128 */
        float* gh  = sm + 49280;    /* 384 */
        for (int i=tid;i<49152;i+=512) whh[i]=d_whhT[i];
        if (tid<128) hv[tid]=h0[tid];
        __syncthreads();
        for (int t=0;t<Tv;t++){
            if (tid<384){
                float acc = bhh[tid];
                #pragma unroll 8
                for (int j=0;j<128;j++) acc += whh[j*384+tid]*hv[j];
                gh[tid]=acc;
            }
            __syncthreads();
            if (tid<128){
                const float* gx = d_gx + (b*Tv+t)*384;
                float r = sigm(gx[tid]     + gh[tid]);
                float z = sigm(gx[128+tid] + gh[128+tid]);
                float n = tanhf(gx[256+tid] + r*gh[256+tid]);
                float hn = (1.f-z)*n + z*hv[tid];
                hv[tid]=hn;
                d_gruout[(b*Tv+t)*128+tid]=hn;
            }
            __syncthreads();
        }
    }
}

/* ---------------- prediction head ---------------- */
__global__ void __launch_bounds__(256) final_kernel(
    const int* e_data, const float* eemb_w, const float* Wp, const float* bp,
    const float* Wp1, const float* bp1, float* out)
{
    int w = blockIdx.x*8 + (threadIdx.x>>5);
    int lane = threadIdx.x & 31;
    if (w >= Bv*(Tv-1)) return;
    int b = w/(Tv-1), tm = w%(Tv-1); int t1 = tm+1;
    int e = e_data[b*Tv + t1];
    float a0=0.f, a1=0.f;
    for (int d=lane; d<384; d+=32){
        float xo = 0.f;
        if (d<128)       xo = d_gruout[(b*Tv+tm)*128+d];
        else if (d<256)  xo = d_out1[(b*(Tv-1)+tm)*128 + d-128];
        float x  = (d<256)? xo : eemb_w[e*128 + d-256];
        float x1 = (d<256)? xo : d_sedata[(b*Tv+t1)*128 + d-256];
        a0 += Wp[d]*x; a1 += Wp1[d]*x1;
    }
    #pragma unroll
    for (int off=16;off;off>>=1){
        a0 += __shfl_down_sync(0xffffffffu,a0,off);
        a1 += __shfl_down_sync(0xffffffffu,a1,off);
    }
    if (lane==0){
        float r  = sigm(a0+bp[0]);
        float r1 = sigm(a1+bp1[0]);
        out[b*Tv + t1] = r*r1;
        if (tm==0) out[b*Tv] = 0.f;
    }
}

/* ---------------- launch ---------------- */
extern "C" void kernel_launch(void* const* d_in, const int* in_sizes, int n_in,
                              void* d_out, int out_size)
{
    const int*   a_data   = (const int*)  d_in[1];
    const int*   e_data   = (const int*)  d_in[2];
    const float* q_matrix = (const float*)d_in[4];
    const float* semb_w   = (const float*)d_in[5];
    const float* aemb_w   = (const float*)d_in[6];
    const float* eemb_w   = (const float*)d_in[7];
    const float* W1=(const float*)d_in[8];  const float* b1=(const float*)d_in[9];
    const float* W2=(const float*)d_in[10]; const float* b2=(const float*)d_in[11];
    const float* W3=(const float*)d_in[12]; const float* b3=(const float*)d_in[13];
    const float* key=(const float*)d_in[14];
    const float* wih=(const float*)d_in[15]; const float* whh=(const float*)d_in[16];
    const float* bih=(const float*)d_in[17]; const float* bhh=(const float*)d_in[18];
    const float* Wg=(const float*)d_in[19];  const float* bg=(const float*)d_in[20];
    const float* Wgg=(const float*)d_in[21]; const float* bgg=(const float*)d_in[22];
    const float* Wf=(const float*)d_in[23];  const float* bf=(const float*)d_in[24];
    const float* Wp=(const float*)d_in[25];  const float* bp=(const float*)d_in[26];
    const float* Wp1=(const float*)d_in[27]; const float* bp1=(const float*)d_in[28];
    const float* h0=(const float*)d_in[29];  const float* m0=(const float*)d_in[30];
    float* out = (float*)d_out;

    cudaFuncSetAttribute(scan_kernel, cudaFuncAttributeMaxDynamicSharedMemorySize,
                         SMEM_FLOATS*(int)sizeof(float));

    prep_kernel <<<64,  256>>>(W1,W2,W3,key,wih,whh,Wg,Wgg,Wf);
    fused_kernel<<<2000,256>>>(e_data,a_data,q_matrix,semb_w,aemb_w,eemb_w,
                               b1,b2,b3,bih,bg,bgg);
    scan_kernel <<<192, 512, SMEM_FLOATS*(int)sizeof(float)>>>(h0,m0,bf,bhh);
    final_kernel<<<3992,256>>>(e_data,eemb_w,Wp,bp,Wp1,bp1,out);
}

// round 8
// speedup vs baseline: 1.1972x; 1.1972x over previous
#include <cuda_runtime.h>
#include <math.h>

#define Bv   64
#define Tv   500
#define Hh   128
#define Kk   32
#define NSK  101    /* N_SK+1 */
#define BT   (Bv*Tv)

typedef unsigned long long ull;

/* ---------------- scratch (device globals; no allocation) ---------------- */
__device__ float d_sedata [BT*Hh];
__device__ float d_selearn[BT*Hh];
__device__ float d_gx     [BT*3*Hh];
__device__ float d_preg   [BT*Hh];
__device__ float d_pregg  [BT*Hh];
__device__ float d_wall   [BT*Kk];
__device__ float d_gruout [BT*Hh];
__device__ float d_out1   [Bv*(Tv-1)*Hh];

__device__ float d_W1T [256*128];
__device__ float d_W2T [384*128];
__device__ float d_W3T [256*128];
__device__ float d_WihT[128*384];
__device__ float d_keyT[128*32];
__device__ float d_WGgP[128*256];   /* pair-interleaved: (j,o) -> [(j>>1)*512 + o*2 + (j&1)] */
__device__ float d_WgTl [128*128];
__device__ float d_WggTl[128*128];
__device__ float d_WfaP [128*128];  /* Wf[:, :128] pair-interleaved: [(j>>1)*256 + h*2 + (j&1)] */
__device__ float d_WfbP [128*128];  /* Wf[:, 128:] pair-interleaved */
__device__ float d_whhT [128*384];

__device__ __forceinline__ float sigm(float x){ return 1.f/(1.f+expf(-x)); }

/* ---- MUFU-free sigmoid: exp2 via integer-split + deg-6 Taylor; recip via Newton ---- */
__device__ __forceinline__ float fsigm(float x){
    float z = -x * 1.4426950408889634f;        /* -x*log2(e) */
    z = fminf(fmaxf(z, -126.f), 126.f);
    float fn = z + 12582912.f;                 /* 1.5*2^23 magic */
    int   iz = __float_as_int(fn);
    float n  = fn - 12582912.f;
    float u  = (z - n) * 0.6931471805599453f;  /* f*ln2, f in [-0.5,0.5] */
    float p  = 1.3888889e-3f;
    p = fmaf(p, u, 8.3333333e-3f);
    p = fmaf(p, u, 4.1666667e-2f);
    p = fmaf(p, u, 1.6666667e-1f);
    p = fmaf(p, u, 0.5f);
    p = fmaf(p, u, 1.0f);
    p = fmaf(p, u, 1.0f);
    float s = __int_as_float((iz - 1262485377) << 23);   /* 2^n : (n+127)<<23 */
    float d = fmaf(p, s, 1.0f);                /* 1 + e^{-x} */
    float r = __int_as_float(0x7EF311C3 - __float_as_int(d));
    r = r * (2.0f - d*r);
    r = r * (2.0f - d*r);
    r = r * (2.0f - d*r);
    return r;
}
__device__ __forceinline__ float ftanh(float x){ return fmaf(2.f, fsigm(2.f*x), -1.f); }

__device__ __forceinline__ void fma2(ull &d, ull a, ull b){
    asm("fma.rn.f32x2 %0, %1, %2, %0;" : "+l"(d) : "l"(a), "l"(b));
}
__device__ __forceinline__ float sum2(ull v){
    return __uint_as_float((unsigned)v) + __uint_as_float((unsigned)(v>>32));
}

/* hs swizzle: logical (k,h) -> float index. chunk (h>>2) XORed with (k>>2)&7 */
__device__ __forceinline__ int hsw(int k, int h){
    return k*128 + ((((h>>2) ^ ((k>>2)&7)))<<2) + (h&3);
}

/* ---------------- weight pre-transpose / pair-interleave ---------------- */
__global__ void prep_kernel(const float* W1, const float* W2, const float* W3,
                            const float* key, const float* wih, const float* whh,
                            const float* Wg, const float* Wgg, const float* Wf)
{
    int stride = gridDim.x*blockDim.x;
    int t0 = blockIdx.x*blockDim.x + threadIdx.x;
    for (int i=t0;i<256*128;i+=stride){ int j=i>>7,h=i&127; d_W1T[i]=W1[h*256+j]; d_W3T[i]=W3[h*256+j]; }
    for (int i=t0;i<384*128;i+=stride){ int j=i>>7,h=i&127; d_W2T[i]=W2[h*384+j]; }
    for (int i=t0;i<128*384;i+=stride){ int h=i/384,g=i%384; d_WihT[i]=wih[g*128+h]; d_whhT[i]=whh[g*128+h]; }
    for (int i=t0;i<128*32;i+=stride){ int h=i>>5,k=i&31; d_keyT[i]=key[k*128+h]; }
    for (int i=t0;i<128*256;i+=stride){ int j=i>>8,o=i&255;
        d_WGgP[(j>>1)*512 + o*2 + (j&1)] = (o<128)? Wg[o*256+j] : Wgg[(o-128)*256+j]; }
    for (int i=t0;i<128*128;i+=stride){ int j=i>>7,h=i&127;
        d_WgTl[i]=Wg[h*256+128+j]; d_WggTl[i]=Wgg[h*256+128+j];
        d_WfaP[(j>>1)*256 + h*2 + (j&1)] = Wf[h*256+j];
        d_WfbP[(j>>1)*256 + h*2 + (j&1)] = Wf[h*256+128+j]; }
}

/* ---------------- fused parallel phase (unchanged, passing) ---------------- */
__global__ void __launch_bounds__(256) fused_kernel(
    const int* e_data, const int* a_data, const float* qm, const float* semb_w,
    const float* aemb_w, const float* eemb_w,
    const float* b1, const float* b2, const float* b3,
    const float* bih, const float* bg, const float* bgg)
{
    __shared__ float X [16*384];
    __shared__ float sd[16*128];
    __shared__ float sl[16*128];
    int tid = threadIdx.x;
    int h = tid & 127, rh = tid >> 7;
    int base = blockIdx.x*16;
    int rbase = rh*8;

    for (int r8=0;r8<8;r8++){
        int rr = rbase + r8; int row = base + rr;
        int e = e_data[row], a = a_data[row];
        const float* qrow = qm + (size_t)e*NSK;
        float acc=0.f, cnt=0.f;
        #pragma unroll 4
        for (int s=0;s<NSK;s++){ float q = qrow[s]; acc += q*semb_w[s*128+h]; cnt += q; }
        if (cnt==0.f) cnt=1.f;
        X[rr*384+h]       = acc/cnt;
        X[rr*384+128+h]   = eemb_w[e*128+h];
        X[rr*384+256+h]   = aemb_w[a*128+h];
    }
    __syncthreads();

    {
        float acc[8];
        #pragma unroll
        for(int r=0;r<8;r++)acc[r]=b1[h];
        #pragma unroll 4
        for (int j=0;j<256;j++){ float w = d_W1T[j*128+h];
            #pragma unroll
            for (int r=0;r<8;r++) acc[r] += X[(rbase+r)*384 + j]*w; }
        #pragma unroll
        for (int r=0;r<8;r++){ float v=fmaxf(acc[r],0.f);
            sd[(rbase+r)*128+h]=v; d_sedata[(base+rbase+r)*128+h]=v; }
    }
    {
        float acc[8];
        #pragma unroll
        for(int r=0;r<8;r++)acc[r]=b2[h];
        #pragma unroll 4
        for (int j=0;j<384;j++){ float w = d_W2T[j*128+h];
            #pragma unroll
            for (int r=0;r<8;r++) acc[r] += X[(rbase+r)*384 + j]*w; }
        #pragma unroll
        for (int r=0;r<8;r++){ float v=fmaxf(acc[r],0.f);
            sl[(rbase+r)*128+h]=v; d_selearn[(base+rbase+r)*128+h]=v; }
    }
    float el[8];
    {
        float acc[8];
        #pragma unroll
        for(int r=0;r<8;r++)acc[r]=b3[h];
        #pragma unroll 4
        for (int j=0;j<256;j++){ float w = d_W3T[j*128+h];
            #pragma unroll
            for (int r=0;r<8;r++) acc[r] += X[(rbase+r)*384 + 128 + j]*w; }
        #pragma unroll
        for (int r=0;r<8;r++) el[r] = fmaxf(acc[r],0.f);
    }
    __syncthreads();
    #pragma unroll
    for (int r=0;r<8;r++) X[(rbase+r)*128 + h] = el[r];
    __syncthreads();

    for (int p=0;p<3;p++){
        int g = p*128+h;
        float acc[8];
        #pragma unroll
        for(int r=0;r<8;r++)acc[r]=bih[g];
        #pragma unroll 4
        for (int j=0;j<128;j++){ float w = d_WihT[j*384+g];
            #pragma unroll
            for (int r=0;r<8;r++) acc[r] += X[(rbase+r)*128+j]*w; }
        #pragma unroll
        for (int r=0;r<8;r++) d_gx[(base+rbase+r)*384 + g] = acc[r];
    }
    {
        float a1[8],a2[8];
        #pragma unroll
        for(int r=0;r<8;r++){a1[r]=bg[h]; a2[r]=bgg[h];}
        #pragma unroll 4
        for (int j=0;j<128;j++){ float w1=d_WgTl[j*128+h], w2=d_WggTl[j*128+h];
            #pragma unroll
            for (int r=0;r<8;r++){ float x=sl[(rbase+r)*128+j]; a1[r]+=x*w1; a2[r]+=x*w2; } }
        #pragma unroll
        for (int r=0;r<8;r++){ d_preg[(base+rbase+r)*128+h]=a1[r]; d_pregg[(base+rbase+r)*128+h]=a2[r]; }
    }
    if (tid < 64){
        int k = tid & 31; int rh2 = tid >> 5; int rb2 = rh2*8;
        float acc[8];
        #pragma unroll
        for(int r=0;r<8;r++)acc[r]=0.f;
        #pragma unroll 4
        for (int j=0;j<128;j++){ float w = d_keyT[j*32+k];
            #pragma unroll
            for (int r=0;r<8;r++) acc[r] += sd[(rb2+r)*128+j]*w; }
        #pragma unroll
        for (int r=0;r<8;r++) d_wall[(base+rb2+r)*32 + k] = acc[r];
    }
}

/* ---------------- dummy (profiling alignment: puts scan at ncu -s 5) ---------------- */
__global__ void dummy_kernel(){}

/* ---------------- sequential scans (512 threads, warp-specialized) ---------------- */
#define SMEM_FLOATS 53888   /* 215552 bytes */

__global__ void __launch_bounds__(512) scan_kernel(
    const float* h0, const float* m0, const float* bf, const float* bhh)
{
    extern __shared__ float sm[];
    int tid = threadIdx.x;
    int b = blockIdx.x & 63;

    if (blockIdx.x < 64) {
        /* ------------- memory scan: warps 0-7 = GEMM+epilogue, warps 8-15 = gates ------------- */
        float* WGg = sm;             /* 32768 : pair-interleaved gate weights */
        float* Wfa = sm + 32768;     /* 16384 : pair-interleaved Wf_a */
        float* hs  = sm + 49152;     /* 4096  : h state, XOR-swizzled rows */
        float* htv = sm + 53248;     /* 128 */
        float* LG  = sm + 53376;     /* 128 */
        float* cv  = sm + 53504;     /* 128 */
        float* gA  = sm + 53632;     /* 256 : gate preacts */

        for (int i=tid;i<32768;i+=512) WGg[i] = d_WGgP[i];
        for (int i=tid;i<16384;i+=512) Wfa[i] = d_WfaP[i];
        for (int i=tid;i<4096; i+=512){ int k=i>>7, h=i&127; hs[hsw(k,h)] = m0[i]; }
        __syncthreads();

        /* ht0 = Wall[b,0] . h_pre0 */
        if (tid < 128){
            float acc=0.f; const float* w0 = d_wall + b*Tv*Kk;
            #pragma unroll 8
            for (int k=0;k<32;k++) acc += w0[k]*hs[hsw(k,tid)];
            htv[tid]=acc;
        }
        __syncthreads();

        if (tid < 256){
            /* =================== C-group: GEMM + epilogue =================== */
            int w = tid >> 5, l = tid & 31;
            int kq = l >> 2, hq = w*4 + (l & 3);
            int k0 = kq*4, h0i = hq*4;
            int pc = ((hq ^ kq) & 31) << 2;      /* physical chunk offset for my h-chunk */

            float4 wA4 = *(const float4*)&d_wall[(b*Tv  )*32 + k0];
            float4 wB4 = *(const float4*)&d_wall[(b*Tv+1)*32 + k0];

            for (int t=0;t<Tv-1;t++){
                /* main GEMM: acc[k][h] = h_pre[k,:] . Wf_a[:,h], f32x2 over j pairs */
                ull acc2[4][4];
                #pragma unroll
                for (int a=0;a<4;a++){
                    #pragma unroll
                    for (int c=0;c<4;c++) acc2[a][c]=0ull;
                }
                {
                    const float* wbase = Wfa + h0i*2;
                    #pragma unroll 4
                    for (int jg=0;jg<32;jg++){
                        float4 wA0 = *(const float4*)&wbase[(2*jg  )*256];
                        float4 wB0 = *(const float4*)&wbase[(2*jg  )*256 + 4];
                        float4 wA1 = *(const float4*)&wbase[(2*jg+1)*256];
                        float4 wB1 = *(const float4*)&wbase[(2*jg+1)*256 + 4];
                        ull wA0a = ((ull*)&wA0)[0], wA0b = ((ull*)&wA0)[1];
                        ull wB0a = ((ull*)&wB0)[0], wB0b = ((ull*)&wB0)[1];
                        ull wA1a = ((ull*)&wA1)[0], wA1b = ((ull*)&wA1)[1];
                        ull wB1a = ((ull*)&wB1)[0], wB1b = ((ull*)&wB1)[1];
                        int sc = ((jg ^ kq) << 2);   /* swizzled chunk for this jg */
                        #pragma unroll
                        for (int kk=0;kk<4;kk++){
                            float4 hp4 = *(const float4*)&hs[(k0+kk)*128 + sc];
                            ull hp01 = ((ull*)&hp4)[0], hp23 = ((ull*)&hp4)[1];
                            fma2(acc2[kk][0], hp01, wA0a);
                            fma2(acc2[kk][1], hp01, wA0b);
                            fma2(acc2[kk][2], hp01, wB0a);
                            fma2(acc2[kk][3], hp01, wB0b);
                            fma2(acc2[kk][0], hp23, wA1a);
                            fma2(acc2[kk][1], hp23, wA1b);
                            fma2(acc2[kk][2], hp23, wB1a);
                            fma2(acc2[kk][3], hp23, wB1b);
                        }
                    }
                }
                /* wait for AB-group: LG + cv ready */
                asm volatile("bar.sync 2, 512;" ::: "memory");

                {
                    float lg0 = LG[h0i+0], lg1 = LG[h0i+1], lg2v = LG[h0i+2], lg3 = LG[h0i+3];
                    float cv0 = cv[h0i+0], cv1 = cv[h0i+1], cv2 = cv[h0i+2], cv3 = cv[h0i+3];
                    float pr[4]={0.f,0.f,0.f,0.f};
                    #pragma unroll
                    for (int kk=0;kk<4;kk++){
                        float wtk = ((const float*)&wA4)[kk];
                        float wnk = ((const float*)&wB4)[kk];
                        float* row = &hs[(k0+kk)*128 + pc];
                        float4 hv4 = *(float4*)row;
                        float4 nv;
                        nv.x = fsigm(sum2(acc2[kk][0]) + cv0)*hv4.x + wtk*lg0;
                        nv.y = fsigm(sum2(acc2[kk][1]) + cv1)*hv4.y + wtk*lg1;
                        nv.z = fsigm(sum2(acc2[kk][2]) + cv2)*hv4.z + wtk*lg2v;
                        nv.w = fsigm(sum2(acc2[kk][3]) + cv3)*hv4.w + wtk*lg3;
                        *(float4*)row = nv;
                        pr[0] += wnk*nv.x; pr[1] += wnk*nv.y;
                        pr[2] += wnk*nv.z; pr[3] += wnk*nv.w;
                    }
                    #pragma unroll
                    for (int off=16;off>=4;off>>=1){
                        #pragma unroll
                        for (int a=0;a<4;a++) pr[a] += __shfl_xor_sync(0xffffffffu, pr[a], off);
                    }
                    if (l < 4){
                        float4 st; st.x=pr[0]; st.y=pr[1]; st.z=pr[2]; st.w=pr[3];
                        int hb = (w*4 + l)*4;
                        *(float4*)&htv[hb] = st;
                        *(float4*)&d_out1[(b*(Tv-1)+t)*128 + hb] = st;
                    }
                    wA4 = wB4;
                    if (t+2 < Tv) wB4 = *(const float4*)&d_wall[(b*Tv+t+2)*32 + k0];
                }
                __syncthreads();   /* htv/hs visible to everyone for next step */
            }
        } else {
            /* =================== AB-group: gate dots + LG + cv =================== */
            int o = tid - 256;                 /* 0..255 */
            float pfg=0.f, pfgg=0.f;
            if (o < 128){
                pfg  = d_preg [(b*Tv)*128+o];
                pfgg = d_pregg[(b*Tv)*128+o];
            }
            for (int t=0;t<Tv-1;t++){
                /* A) gate preact: one full f32x2 dot per thread */
                {
                    ull acc = 0;
                    const float* wrow = WGg + o*2;
                    #pragma unroll 16
                    for (int jp=0;jp<64;jp++){
                        ull h2 = *(const ull*)&htv[jp*2];
                        ull w2 = *(const ull*)&wrow[jp*512];
                        fma2(acc, h2, w2);
                    }
                    gA[o] = sum2(acc);
                }
                asm volatile("bar.sync 1, 256;" ::: "memory");
                if (o < 128){
                    LG[o] = ftanh(gA[o]+pfg)*fsigm(gA[128+o]+pfgg);
                    pfg  = d_preg [(b*Tv+t+1)*128+o];
                    pfgg = d_pregg[(b*Tv+t+1)*128+o];
                    asm volatile("bar.sync 3, 128;" ::: "memory");
                    /* B) cv = Wf_b @ LG + bf (weights streamed from L2) */
                    ull acc = 0;
                    const float* wrow = d_WfbP + o*2;
                    #pragma unroll 16
                    for (int jp=0;jp<64;jp++){
                        ull lg2 = *(const ull*)&LG[jp*2];
                        ull w2  = *(const ull*)&wrow[jp*256];
                        fma2(acc, lg2, w2);
                    }
                    cv[o] = sum2(acc) + bf[o];
                }
                /* hand results to C-group (non-blocking) */
                asm volatile("bar.arrive 2, 512;" ::: "memory");
                __syncthreads();   /* wait for epilogue: htv updated */
            }
        }
    } else {
        /* ------------- GRU scan (one batch per CTA) ------------- */
        float* whh = sm;            /* 49152 : w_hh^T [j][384] */
        float* hv  = sm + 49152;    /* 128 */
        float* gh  = sm + 49280;    /* 384 */
        for (int i=tid;i<49152;i+=512) whh[i]=d_whhT[i];
        if (tid<128) hv[tid]=h0[tid];
        __syncthreads();
        for (int t=0;t<Tv;t++){
            if (tid<384){
                float acc = bhh[tid];
                #pragma unroll 8
                for (int j=0;j<128;j++) acc += whh[j*384+tid]*hv[j];
                gh[tid]=acc;
            }
            __syncthreads();
            if (tid<128){
                const float* gx = d_gx + (b*Tv+t)*384;
                float r = sigm(gx[tid]     + gh[tid]);
                float z = sigm(gx[128+tid] + gh[128+tid]);
                float n = tanhf(gx[256+tid] + r*gh[256+tid]);
                float hn = (1.f-z)*n + z*hv[tid];
                hv[tid]=hn;
                d_gruout[(b*Tv+t)*128+tid]=hn;
            }
            __syncthreads();
        }
    }
}

/* ---------------- prediction head ---------------- */
__global__ void __launch_bounds__(256) final_kernel(
    const int* e_data, const float* eemb_w, const float* Wp, const float* bp,
    const float* Wp1, const float* bp1, float* out)
{
    int w = blockIdx.x*8 + (threadIdx.x>>5);
    int lane = threadIdx.x & 31;
    if (w >= Bv*(Tv-1)) return;
    int b = w/(Tv-1), tm = w%(Tv-1); int t1 = tm+1;
    int e = e_data[b*Tv + t1];
    float a0=0.f, a1=0.f;
    for (int d=lane; d<384; d+=32){
        float xo = 0.f;
        if (d<128)       xo = d_gruout[(b*Tv+tm)*128+d];
        else if (d<256)  xo = d_out1[(b*(Tv-1)+tm)*128 + d-128];
        float x  = (d<256)? xo : eemb_w[e*128 + d-256];
        float x1 = (d<256)? xo : d_sedata[(b*Tv+t1)*128 + d-256];
        a0 += Wp[d]*x; a1 += Wp1[d]*x1;
    }
    #pragma unroll
    for (int off=16;off;off>>=1){
        a0 += __shfl_down_sync(0xffffffffu,a0,off);
        a1 += __shfl_down_sync(0xffffffffu,a1,off);
    }
    if (lane==0){
        float r  = sigm(a0+bp[0]);
        float r1 = sigm(a1+bp1[0]);
        out[b*Tv + t1] = r*r1;
        if (tm==0) out[b*Tv] = 0.f;
    }
}

/* ---------------- launch ---------------- */
extern "C" void kernel_launch(void* const* d_in, const int* in_sizes, int n_in,
                              void* d_out, int out_size)
{
    const int*   a_data   = (const int*)  d_in[1];
    const int*   e_data   = (const int*)  d_in[2];
    const float* q_matrix = (const float*)d_in[4];
    const float* semb_w   = (const float*)d_in[5];
    const float* aemb_w   = (const float*)d_in[6];
    const float* eemb_w   = (const float*)d_in[7];
    const float* W1=(const float*)d_in[8];  const float* b1=(const float*)d_in[9];
    const float* W2=(const float*)d_in[10]; const float* b2=(const float*)d_in[11];
    const float* W3=(const float*)d_in[12]; const float* b3=(const float*)d_in[13];
    const float* key=(const float*)d_in[14];
    const float* wih=(const float*)d_in[15]; const float* whh=(const float*)d_in[16];
    const float* bih=(const float*)d_in[17]; const float* bhh=(const float*)d_in[18];
    const float* Wg=(const float*)d_in[19];  const float* bg=(const float*)d_in[20];
    const float* Wgg=(const float*)d_in[21]; const float* bgg=(const float*)d_in[22];
    const float* Wf=(const float*)d_in[23];  const float* bf=(const float*)d_in[24];
    const float* Wp=(const float*)d_in[25];  const float* bp=(const float*)d_in[26];
    const float* Wp1=(const float*)d_in[27]; const float* bp1=(const float*)d_in[28];
    const float* h0=(const float*)d_in[29];  const float* m0=(const float*)d_in[30];
    float* out = (float*)d_out;

    cudaFuncSetAttribute(scan_kernel, cudaFuncAttributeMaxDynamicSharedMemorySize,
                         SMEM_FLOATS*(int)sizeof(float));

    prep_kernel <<<64,  256>>>(W1,W2,W3,key,wih,whh,Wg,Wgg,Wf);
    fused_kernel<<<2000,256>>>(e_data,a_data,q_matrix,semb_w,aemb_w,eemb_w,
                               b1,b2,b3,bih,bg,bgg);
    /* dummies align scan_kernel onto ncu's -s 5 -c 1 capture window */
    dummy_kernel<<<1,32>>>();
    dummy_kernel<<<1,32>>>();
    dummy_kernel<<<1,32>>>();
    scan_kernel <<<128, 512, SMEM_FLOATS*(int)sizeof(float)>>>(h0,m0,bf,bhh);
    final_kernel<<<3992,256>>>(e_data,eemb_w,Wp,bp,Wp1,bp1,out);
}